// round 14
// baseline (speedup 1.0000x reference)
#include <cuda_runtime.h>
#include <cstdint>

static __device__ __forceinline__ double u64_as_double(uint64_t u) {
    return __longlong_as_double((long long)u);
}
static __device__ __forceinline__ uint64_t double_as_u64(double d) {
    return (uint64_t)__double_as_longlong(d);
}
static __device__ __forceinline__ double rsqrt_approx(double v) {
    double r;
    asm("rsqrt.approx.ftz.f64 %0, %1;" : "=d"(r) : "d"(v));
    return r;
}
// Exact multiply by 0.5 for a normal double (exponent decrement, ALU pipe).
static __device__ __forceinline__ double halve(double s) {
    return __hiloint2double(__double2hiint(s) - 0x00100000, __double2loint(s));
}

#define SQRT2_MANT 1865452045155277ULL
#define NAN_BITS   0x7FF8000000000000ULL
#define INF_BITS   0x7FF0000000000000ULL
#define MANT_MASK  0xFFFFFFFFFFFFFULL
#define FONE       0x3F800000u

// Persistent launch: exactly one wave of CTAs (148 SMs x 8 blocks/SM).
#define PERSIST_BLOCKS (148 * 8)

__global__ void __launch_bounds__(256, 8)
spike_sqrt_kernel(const float* __restrict__ x, float* __restrict__ out, int n)
{
    const int lane    = threadIdx.x & 31;
    const int warp0   = (blockIdx.x * blockDim.x + threadIdx.x) >> 5;
    const int nWarps  = (gridDim.x * blockDim.x) >> 5;
    const int nTiles  = n >> 5;                 // 32 rows per warp-tile

    for (int t = warp0; t < nTiles; t += nWarps) {
        const int warpRow0 = t << 5;

        // ---------------- pack: ballot transpose, fully coalesced ------------
        // Iter k loads 32 consecutive floats = half of row k>>1; ballot gives
        // those 32 bits; streaming hint (each line read exactly once).
        const float* tile = x + (size_t)warpRow0 * 64;
        unsigned hi = 0, lo = 0;
        #pragma unroll
        for (int k = 0; k < 64; k++) {
            float v = __ldcs(tile + k * 32 + lane);
            unsigned mask = __ballot_sync(0xffffffffu, v > 0.5f);
            unsigned w = __brev(mask);
            if ((k >> 1) == lane) { if (k & 1) lo = w; else hi = w; }
        }
        const uint64_t u = ((uint64_t)hi << 32) | lo;

        // ---------------- normalized frame: f = 2^(2k) * m,  m in [1,4) -----
        const long long e_x    = (long long)((u >> 52) & 0x7FFULL);
        const long long e_real = e_x - 1023;
        const long long oddb   = (e_real & 1);
        const long long kk     = (e_real >> 1);             // arithmetic shift
        const double m = u64_as_double((u & MANT_MASK) | ((uint64_t)(1023 + oddb) << 52));

        // ---------------- rsqrt sprint to the y4 region ----------------------
        // Any point within ~2^-43 of sqrt(m) yields bit-identical y5, y6
        // (Newton contraction: pre-round images differ by ~e^2 <= 2^-86).
        // rsqrt NR: delta -> 1.5*delta^2; 3 steps floor at ~2^-51.5.
        double r = rsqrt_approx(m);
        #pragma unroll
        for (int i = 0; i < 3; i++) {
            double tt = m * r;
            double e  = __fma_rn(-tt, r, 1.0);
            r = __fma_rn(halve(r), e, r);   // halve(r): exact, integer pipe
        }
        double y4 = m * r;                   // RN(m*r): within ~2^-51 of sqrt(m)

        // ---------------- last two Newton iterations, bit-exact --------------
        // q0 = RN(m*r) == y4 for both divisions, so each CR quotient is a
        // single Markstein correction (eps_pre ~ 2^-101 -> CR).
        double q1 = __fma_rn(__fma_rn(-y4, y4, m), r, y4);   // RN(m / y4)
        double y5 = halve(y4 + q1);                           // reference i=4 image
        double q2 = __fma_rn(__fma_rn(-y5, y4, m), r, y4);   // RN(m / y5)
        double y6 = halve(y5 + q2);                           // == y12 (even tail)

        // Re-apply exponent: 2^kk = integer add on the exponent field (exact,
        // including the carry when y == 2.0).
        uint64_t rbits = double_as_u64(y6) + ((uint64_t)kk << 52);

        // ---------------- special-case muxes (same order as reference) -------
        const uint64_t s_bit  = u >> 63;
        const bool m_any      = (u & MANT_MASK) != 0ULL;
        const bool e_all_one  = (e_x == 0x7FF);
        const bool e_is_zero  = (e_x == 0);
        if (s_bit)                              rbits = NAN_BITS;
        if (e_all_one &&  m_any)                rbits = NAN_BITS;
        if (e_all_one && !m_any && s_bit == 0)  rbits = INF_BITS;
        if (e_is_zero && !m_any)                rbits = 0ULL;

        // ---------------- unpack: shuffle + uint4 stores, fully coalesced ----
        // Lane writes the 4 floats at flat j*128 + 4*lane; bits live in word
        // k = 4j+(lane>>3) (source lane 2j+(lane>>4), parity (lane>>3)&1) at
        // offset 28-4*(lane&7). Integer select avoids the conversion pipe;
        // streaming store (write-once data).
        const unsigned rhi = (unsigned)(rbits >> 32);
        const unsigned rlo = (unsigned)rbits;
        uint4* otile4 = (uint4*)(out + (size_t)warpRow0 * 64);
        const int src    = lane >> 4;
        const int parity = (lane >> 3) & 1;
        const int sh     = 28 - 4 * (lane & 7);
        #pragma unroll
        for (int j = 0; j < 16; j++) {
            unsigned whi = __shfl_sync(0xffffffffu, rhi, 2 * j + src);
            unsigned wlo = __shfl_sync(0xffffffffu, rlo, 2 * j + src);
            unsigned w   = parity ? wlo : whi;
            unsigned b   = w >> sh;          // my 4 bits in b[3..0], MSB first
            uint4 v;
            v.x = ((b >> 3) & 1u) * FONE;
            v.y = ((b >> 2) & 1u) * FONE;
            v.z = ((b >> 1) & 1u) * FONE;
            v.w = (b & 1u) * FONE;
            __stcs(&otile4[j * 32 + lane], v);
        }
    }
}

extern "C" void kernel_launch(void* const* d_in, const int* in_sizes, int n_in,
                              void* d_out, int out_size)
{
    const float* x = (const float*)d_in[0];
    float* out = (float*)d_out;
    const int n = in_sizes[0] / 64;
    const int nTiles = (n + 31) / 32;
    int blocks = (nTiles + 7) / 8;                  // 8 warp-tiles per block
    if (blocks > PERSIST_BLOCKS) blocks = PERSIST_BLOCKS;
    spike_sqrt_kernel<<<blocks, 256>>>(x, out, n);
}

// round 15
// speedup vs baseline: 1.8076x; 1.8076x over previous
#include <cuda_runtime.h>
#include <cstdint>

static __device__ __forceinline__ double u64_as_double(uint64_t u) {
    return __longlong_as_double((long long)u);
}
static __device__ __forceinline__ uint64_t double_as_u64(double d) {
    return (uint64_t)__double_as_longlong(d);
}
static __device__ __forceinline__ double rsqrt_approx(double v) {
    double r;
    asm("rsqrt.approx.ftz.f64 %0, %1;" : "=d"(r) : "d"(v));
    return r;
}
// Exact multiply by 0.5 for a normal double (exponent decrement, ALU pipe).
static __device__ __forceinline__ double halve(double s) {
    return __hiloint2double(__double2hiint(s) - 0x00100000, __double2loint(s));
}

#define SQRT2_MANT 1865452045155277ULL
#define NAN_BITS   0x7FF8000000000000ULL
#define INF_BITS   0x7FF0000000000000ULL
#define MANT_MASK  0xFFFFFFFFFFFFFULL
#define FONE       0x3F800000u

__global__ void __launch_bounds__(128, 16)
spike_sqrt_kernel(const float* __restrict__ x, float* __restrict__ out, int n)
{
    const int tid  = blockIdx.x * blockDim.x + threadIdx.x;
    const int lane = threadIdx.x & 31;
    const int warpRow0 = (tid >> 5) << 5;       // first row of this warp's 32-row tile
    if (warpRow0 >= n) return;

    // ---------------- pack: ballot transpose, fully coalesced ----------------
    // Iter k loads 32 consecutive floats = half of row k>>1; ballot gives
    // those 32 bits; streaming hint (each line read exactly once).
    const float* tile = x + (size_t)warpRow0 * 64;
    unsigned hi = 0, lo = 0;
    #pragma unroll
    for (int k = 0; k < 64; k++) {
        float v = __ldcs(tile + k * 32 + lane);
        unsigned mask = __ballot_sync(0xffffffffu, v > 0.5f);
        unsigned w = __brev(mask);
        if ((k >> 1) == lane) { if (k & 1) lo = w; else hi = w; }
    }
    const uint64_t u = ((uint64_t)hi << 32) | lo;

    // ---------------- normalized frame: f = 2^(2k) * m,  m in [1,4) ---------
    const long long e_x    = (long long)((u >> 52) & 0x7FFULL);
    const long long e_real = e_x - 1023;
    const long long oddb   = (e_real & 1);
    const long long kk     = (e_real >> 1);                 // arithmetic shift
    const double m = u64_as_double((u & MANT_MASK) | ((uint64_t)(1023 + oddb) << 52));

    // ---------------- rsqrt sprint to the y4 region -------------------------
    // Any point within ~2^-43 of sqrt(m) yields bit-identical y5, y6 (Newton
    // contraction: pre-round images differ by ~e^2 <= 2^-86). rsqrt NR:
    // delta -> 1.5*delta^2; 3 steps floor at ~2^-51.5 from the MUFU seed.
    double r = rsqrt_approx(m);
    #pragma unroll
    for (int i = 0; i < 3; i++) {
        double t = m * r;
        double e = __fma_rn(-t, r, 1.0);
        r = __fma_rn(halve(r), e, r);       // halve(r): exact, integer pipe
    }
    double y4 = m * r;                       // RN(m*r): within ~2^-51 of sqrt(m)

    // ---------------- last two Newton iterations, bit-exact -----------------
    // q0 = RN(m*r) == y4 for both divisions, so each CR quotient is a single
    // Markstein correction (eps_pre ~ 2^-101 -> CR).
    double q1 = __fma_rn(__fma_rn(-y4, y4, m), r, y4);   // RN(m / y4)
    double y5 = halve(y4 + q1);                           // reference i=4 image
    double q2 = __fma_rn(__fma_rn(-y5, y4, m), r, y4);   // RN(m / y5)
    double y6 = halve(y5 + q2);                           // == y12 (even tail)

    // Re-apply exponent: 2^kk = integer add on the exponent field (exact,
    // including the carry when y == 2.0).
    uint64_t rbits = double_as_u64(y6) + ((uint64_t)kk << 52);

    // ---------------- special-case muxes (same order as reference) ---------
    const uint64_t s_bit  = u >> 63;
    const bool m_any      = (u & MANT_MASK) != 0ULL;
    const bool e_all_one  = (e_x == 0x7FF);
    const bool e_is_zero  = (e_x == 0);
    if (s_bit)                              rbits = NAN_BITS;
    if (e_all_one &&  m_any)                rbits = NAN_BITS;
    if (e_all_one && !m_any && s_bit == 0)  rbits = INF_BITS;
    if (e_is_zero && !m_any)                rbits = 0ULL;

    // ---------------- unpack: shuffle + uint4 stores, fully coalesced -------
    // Lane writes the 4 floats at flat j*128 + 4*lane; bits live in word
    // k = 4j+(lane>>3) (source lane k>>1 = 2j+(lane>>4), parity (lane>>3)&1)
    // at offset 28-4*(lane&7). Integer select (bit * 0x3F800000) avoids the
    // conversion pipe; streaming store (write-once data).
    const unsigned rhi = (unsigned)(rbits >> 32);
    const unsigned rlo = (unsigned)rbits;
    uint4* otile4 = (uint4*)(out + (size_t)warpRow0 * 64);
    const int src    = lane >> 4;
    const int parity = (lane >> 3) & 1;
    const int sh     = 28 - 4 * (lane & 7);
    #pragma unroll
    for (int j = 0; j < 16; j++) {
        unsigned whi = __shfl_sync(0xffffffffu, rhi, 2 * j + src);
        unsigned wlo = __shfl_sync(0xffffffffu, rlo, 2 * j + src);
        unsigned w   = parity ? wlo : whi;
        unsigned b   = w >> sh;              // my 4 bits in b[3..0], MSB first
        uint4 v;
        v.x = ((b >> 3) & 1u) * FONE;
        v.y = ((b >> 2) & 1u) * FONE;
        v.z = ((b >> 1) & 1u) * FONE;
        v.w = (b & 1u) * FONE;
        __stcs(&otile4[j * 32 + lane], v);
    }
}

extern "C" void kernel_launch(void* const* d_in, const int* in_sizes, int n_in,
                              void* d_out, int out_size)
{
    const float* x = (const float*)d_in[0];
    float* out = (float*)d_out;
    const int n = in_sizes[0] / 64;            // number of fp64 elements (rows)
    const int threads = 128;                   // 4 warp-tiles per CTA
    const int rowsPerBlock = (threads / 32) * 32;
    const int blocks = (n + rowsPerBlock - 1) / rowsPerBlock;
    spike_sqrt_kernel<<<blocks, threads>>>(x, out, n);
}